// round 15
// baseline (speedup 1.0000x reference)
#include <cuda_runtime.h>

// Fixed shapes per reference: B=4096, IN=HID=8192, fp32
#define IN_DIM   8192
#define HID_DIM  8192
#define COL4     (IN_DIM / 4)                 // 2048 float4 per row
#define NCHUNK   2
#define CHUNK_F4 (COL4 / NCHUNK)              // 1024 float4 per chunk
#define CS_XBLK  (CHUNK_F4 / 256)             // 4 col-groups per chunk
#define ROW_GRPS 128
#define ROWS_PER_GRP (HID_DIM / ROW_GRPS)     // 64

// Device-global scratch (allocation-free rule: device globals allowed)
__device__ float    g_partial[ROW_GRPS * IN_DIM];   // 4 MB
__device__ float    g_wsum[IN_DIM];                 // 32 KB
__device__ float    g_acc[4096];                    // per-row accumulator
__device__ unsigned g_ctr[NCHUNK * CS_XBLK];        // zero-init; wraps -> replay-safe

// ---- colsum_fused_chunk: col sums of W for chunk c + fused reduce ----
// grid (4, 128) = 512 blocks (full-BW size), block 256. Proven access
// pattern; last-arriving block per column-group reduces 128 partials in
// fixed order and publishes the wsum slice.
__global__ __launch_bounds__(256) void colsum_fused_chunk(
        const float* __restrict__ w, int c) {
    const int t    = threadIdx.x;
    const int col4 = c * CHUNK_F4 + blockIdx.x * 256 + t;
    const int r0   = blockIdx.y * ROWS_PER_GRP;
    const float4* __restrict__ w4 = reinterpret_cast<const float4*>(w);

    float4 acc = make_float4(0.f, 0.f, 0.f, 0.f);
    #pragma unroll 8
    for (int r = 0; r < ROWS_PER_GRP; ++r) {
        float4 v = __ldg(&w4[(size_t)(r0 + r) * COL4 + col4]);
        acc.x += v.x; acc.y += v.y; acc.z += v.z; acc.w += v.w;
    }
    reinterpret_cast<float4*>(g_partial)[(size_t)blockIdx.y * COL4 + col4] = acc;

    __threadfence();
    __syncthreads();

    __shared__ unsigned s_last;
    if (t == 0) {
        unsigned prev = atomicInc(&g_ctr[c * CS_XBLK + blockIdx.x],
                                  ROW_GRPS - 1);           // wraps to 0
        s_last = (prev == ROW_GRPS - 1);
    }
    __syncthreads();

    if (s_last) {
        __threadfence();
        const float4* __restrict__ p4 = reinterpret_cast<const float4*>(g_partial);
        float4 s = make_float4(0.f, 0.f, 0.f, 0.f);
        #pragma unroll 8
        for (int g = 0; g < ROW_GRPS; ++g) {               // fixed order
            float4 v = p4[(size_t)g * COL4 + col4];
            s.x += v.x; s.y += v.y; s.z += v.z; s.w += v.w;
        }
        reinterpret_cast<float4*>(g_wsum)[col4] = s;
    }
}

// ---- rowdot_chunk: R1's proven shape, restricted to chunk c ----
// grid 4096, block 256, 4 LDG.128 per thread on x, one barrier, block exits.
__global__ __launch_bounds__(256) void rowdot_chunk(const float* __restrict__ x,
                                                    float* __restrict__ out,
                                                    int c, int is_last) {
    const int b = blockIdx.x;
    const float4* __restrict__ x4 =
        reinterpret_cast<const float4*>(x + (size_t)b * IN_DIM);
    const float4* __restrict__ w4 = reinterpret_cast<const float4*>(g_wsum);

    float acc = 0.f;
    #pragma unroll
    for (int k = 0; k < CHUNK_F4 / 256; ++k) {   // 4 k-steps
        const int i = c * CHUNK_F4 + threadIdx.x + k * 256;
        float4 xv = __ldg(&x4[i]);
        float4 wv = w4[i];
        acc = fmaf(xv.x, wv.x, acc);
        acc = fmaf(xv.y, wv.y, acc);
        acc = fmaf(xv.z, wv.z, acc);
        acc = fmaf(xv.w, wv.w, acc);
    }

    #pragma unroll
    for (int off = 16; off > 0; off >>= 1)
        acc += __shfl_xor_sync(0xFFFFFFFFu, acc, off);

    __shared__ float warp_sums[8];
    const int lane = threadIdx.x & 31;
    const int wid  = threadIdx.x >> 5;
    if (lane == 0) warp_sums[wid] = acc;
    __syncthreads();

    if (wid == 0) {
        float v = (lane < 8) ? warp_sums[lane] : 0.f;
        #pragma unroll
        for (int off = 4; off > 0; off >>= 1)
            v += __shfl_xor_sync(0xFFFFFFFFu, v, off);
        if (lane == 0) {
            float total = (c == 0) ? v : (g_acc[b] + v);   // c==0 overwrites stale
            if (is_last) out[b] = total * 0.75f;           // (/2) * 1.5
            else         g_acc[b] = total;
        }
    }
}

extern "C" void kernel_launch(void* const* d_in, const int* in_sizes, int n_in,
                              void* d_out, int out_size) {
    const float* x = (const float*)d_in[0];   // [B, IN]
    const float* w = (const float*)d_in[1];   // [HID, IN]
    float* out = (float*)d_out;               // [B, 1]
    const int B = in_sizes[0] / IN_DIM;

    // One-time host-side objects (no device memory)
    static cudaStream_t sA = nullptr;
    static cudaEvent_t  evFork = nullptr;
    static cudaEvent_t  ev[NCHUNK];
    if (!sA) {
        cudaStreamCreateWithFlags(&sA, cudaStreamNonBlocking);
        cudaEventCreateWithFlags(&evFork, cudaEventDisableTiming);
        for (int c = 0; c < NCHUNK; ++c)
            cudaEventCreateWithFlags(&ev[c], cudaEventDisableTiming);
    }

    // Fork producer stream off the capture stream
    cudaEventRecord(evFork, 0);
    cudaStreamWaitEvent(sA, evFork, 0);

    // Producer: two full-BW colsum chunks (512 blocks each), back-to-back
    for (int c = 0; c < NCHUNK; ++c) {
        dim3 g(CS_XBLK, ROW_GRPS);            // (4, 128)
        colsum_fused_chunk<<<g, 256, 0, sA>>>(w, c);
        cudaEventRecord(ev[c], sA);
    }

    // Consumer: rowdot chunk c waits event c; rd0 overlaps cs1.
    for (int c = 0; c < NCHUNK; ++c) {
        cudaStreamWaitEvent(0, ev[c], 0);
        rowdot_chunk<<<B, 256>>>(x, out, c, c == NCHUNK - 1);
    }
}

// round 16
// speedup vs baseline: 1.2617x; 1.2617x over previous
#include <cuda_runtime.h>

// Fixed shapes per reference: B=4096, IN=HID=8192, fp32
#define IN_DIM   8192
#define HID_DIM  8192
#define COL4     (IN_DIM / 4)                    // 2048 float4 per row
#define CS_XBLK  8                               // column groups (8 x 256 f4)
#define ROW_GRPS 128
#define ROWS_PER_GRP (HID_DIM / ROW_GRPS)        // 64 rows per block

// Device-global scratch (allocation-free rule: device globals allowed)
__device__ float    g_partial[ROW_GRPS * IN_DIM];   // 4 MB
__device__ float    g_wsum[IN_DIM];                 // 32 KB
__device__ unsigned g_ctr[CS_XBLK];                 // zero-init; wraps -> replay-safe

// ---------------- Kernel 1: fused colsum (partial + last-block reduce) -------
// grid = (8, 128) = 1024 blocks, block = 256 (proven 81.6%-of-spec pattern).
// After storing its partial, each block signals PDL so rowdot CTAs can begin
// their (wsum-independent) x loads. Last block per column group reduces the
// 128 partials in fixed order -> deterministic wsum.
__global__ __launch_bounds__(256) void colsum_fused(const float* __restrict__ w) {
    const int t    = threadIdx.x;
    const int col4 = blockIdx.x * 256 + t;
    const int r0   = blockIdx.y * ROWS_PER_GRP;
    const float4* __restrict__ w4 = reinterpret_cast<const float4*>(w);

    float4 acc = make_float4(0.f, 0.f, 0.f, 0.f);
    #pragma unroll 8
    for (int r = 0; r < ROWS_PER_GRP; ++r) {
        float4 v = __ldg(&w4[(size_t)(r0 + r) * COL4 + col4]);
        acc.x += v.x; acc.y += v.y; acc.z += v.z; acc.w += v.w;
    }
    reinterpret_cast<float4*>(g_partial)[(size_t)blockIdx.y * COL4 + col4] = acc;

    // Allow the dependent kernel's CTAs to start launching now.
    cudaTriggerProgrammaticLaunchCompletion();

    __threadfence();
    __syncthreads();

    __shared__ unsigned s_last;
    if (t == 0) {
        unsigned prev = atomicInc(&g_ctr[blockIdx.x], ROW_GRPS - 1);  // wraps
        s_last = (prev == ROW_GRPS - 1);
    }
    __syncthreads();

    if (s_last) {
        __threadfence();
        const float4* __restrict__ p4 = reinterpret_cast<const float4*>(g_partial);
        float4 s = make_float4(0.f, 0.f, 0.f, 0.f);
        #pragma unroll 8
        for (int g = 0; g < ROW_GRPS; ++g) {               // fixed order
            float4 v = p4[(size_t)g * COL4 + col4];
            s.x += v.x; s.y += v.y; s.z += v.z; s.w += v.w;
        }
        reinterpret_cast<float4*>(g_wsum)[col4] = s;
    }
}

// ---------------- Kernel 2: PDL rowdot ----------------
// R1's proven shape (one row/block, 256 thr, 8 LDG.128, one barrier), but the
// x loads are issued BEFORE cudaGridDependencySynchronize() so they overlap
// the colsum grid still in flight. wsum is only read after the sync.
__global__ __launch_bounds__(256) void rowdot_pdl(const float* __restrict__ x,
                                                  float* __restrict__ out) {
    const int b = blockIdx.x;
    const float4* __restrict__ x4 =
        reinterpret_cast<const float4*>(x + (size_t)b * IN_DIM);

    // Phase 1: wsum-independent x loads (overlap with colsum)
    float4 xv[COL4 / 256];
    #pragma unroll
    for (int k = 0; k < COL4 / 256; ++k)
        xv[k] = __ldg(&x4[threadIdx.x + k * 256]);

    // Phase 2: wait for the full colsum grid (and its memory) to complete
    cudaGridDependencySynchronize();

    const float4* __restrict__ w4 = reinterpret_cast<const float4*>(g_wsum);
    float acc = 0.f;
    #pragma unroll
    for (int k = 0; k < COL4 / 256; ++k) {
        float4 wv = w4[threadIdx.x + k * 256];
        acc = fmaf(xv[k].x, wv.x, acc);
        acc = fmaf(xv[k].y, wv.y, acc);
        acc = fmaf(xv[k].z, wv.z, acc);
        acc = fmaf(xv[k].w, wv.w, acc);
    }

    #pragma unroll
    for (int off = 16; off > 0; off >>= 1)
        acc += __shfl_xor_sync(0xFFFFFFFFu, acc, off);

    __shared__ float warp_sums[8];
    const int lane = threadIdx.x & 31;
    const int wid  = threadIdx.x >> 5;
    if (lane == 0) warp_sums[wid] = acc;
    __syncthreads();

    if (wid == 0) {
        float v = (lane < 8) ? warp_sums[lane] : 0.f;
        #pragma unroll
        for (int off = 4; off > 0; off >>= 1)
            v += __shfl_xor_sync(0xFFFFFFFFu, v, off);
        if (lane == 0) out[b] = v * 0.75f;   // (/2) * 1.5
    }
}

extern "C" void kernel_launch(void* const* d_in, const int* in_sizes, int n_in,
                              void* d_out, int out_size) {
    const float* x = (const float*)d_in[0];   // [B, IN]
    const float* w = (const float*)d_in[1];   // [HID, IN]
    float* out = (float*)d_out;               // [B, 1]
    const int B = in_sizes[0] / IN_DIM;

    dim3 g1(CS_XBLK, ROW_GRPS);               // (8, 128)
    colsum_fused<<<g1, 256>>>(w);

    // Dependent launch: rowdot CTAs may begin (x loads) while colsum runs;
    // cudaGridDependencySynchronize() inside guards the wsum reads.
    cudaLaunchConfig_t cfg = {};
    cfg.gridDim  = dim3(B, 1, 1);
    cfg.blockDim = dim3(256, 1, 1);
    cudaLaunchAttribute attr[1];
    attr[0].id = cudaLaunchAttributeProgrammaticStreamSerialization;
    attr[0].val.programmaticStreamSerializationAllowed = 1;
    cfg.attrs    = attr;
    cfg.numAttrs = 1;

    cudaError_t err = cudaLaunchKernelEx(&cfg, rowdot_pdl, x, out);
    if (err != cudaSuccess) {
        // Fallback: plain serial launch (correct, ~70 us)
        rowdot_pdl<<<B, 256>>>(x, out);
    }
}

// round 17
// speedup vs baseline: 1.3729x; 1.0881x over previous
#include <cuda_runtime.h>

// Fixed shapes per reference: B=4096, IN=HID=8192, fp32
#define IN_DIM   8192
#define HID_DIM  8192
#define COL4     (IN_DIM / 4)                    // 2048 float4 per row
#define ROW_GRPS 128                             // colsum row groups
#define ROWS_PER_GRP (HID_DIM / ROW_GRPS)        // 64 rows per block

// Device-global scratch (allocation-free rule: device globals allowed)
__device__ float g_partial[ROW_GRPS * IN_DIM];   // 4 MB
__device__ float g_wsum[IN_DIM];                 // 32 KB

// ---------------- Kernel 1: partial column sums of W (frozen, 81.6%) --------
// grid = (8, 128) = 1024 blocks, block = 256.
__global__ __launch_bounds__(256) void colsum_partial(const float* __restrict__ w) {
    const int col4 = blockIdx.x * 256 + threadIdx.x;        // 0..2047
    const int r0   = blockIdx.y * ROWS_PER_GRP;
    const float4* __restrict__ w4 = reinterpret_cast<const float4*>(w);

    float4 acc = make_float4(0.f, 0.f, 0.f, 0.f);
    #pragma unroll 8
    for (int r = 0; r < ROWS_PER_GRP; ++r) {
        float4 v = __ldg(&w4[(size_t)(r0 + r) * COL4 + col4]);
        acc.x += v.x; acc.y += v.y; acc.z += v.z; acc.w += v.w;
    }
    reinterpret_cast<float4*>(g_partial)[(size_t)blockIdx.y * COL4 + col4] = acc;
}

// ---------------- Kernel 2: wide reduce 128 partials -> g_wsum (frozen) ------
// grid = 32, block = 256, ~1 us.
__global__ __launch_bounds__(256) void reduce_partial() {
    const int t    = threadIdx.x;
    const int cl   = t & 63;
    const int gq   = t >> 6;
    const int col4 = blockIdx.x * 64 + cl;
    const float4* __restrict__ p4 = reinterpret_cast<const float4*>(g_partial);

    float4 acc = make_float4(0.f, 0.f, 0.f, 0.f);
    #pragma unroll 8
    for (int i = 0; i < 32; ++i) {
        float4 v = p4[(size_t)(gq * 32 + i) * COL4 + col4];
        acc.x += v.x; acc.y += v.y; acc.z += v.z; acc.w += v.w;
    }

    __shared__ float4 s[4][64];
    s[gq][cl] = acc;
    __syncthreads();

    if (t < 64) {
        float4 a = s[0][t], b = s[1][t], c = s[2][t], d = s[3][t];
        float4 r;
        r.x = (a.x + b.x) + (c.x + d.x);
        r.y = (a.y + b.y) + (c.y + d.y);
        r.z = (a.z + b.z) + (c.z + d.z);
        r.w = (a.w + b.w) + (c.w + d.w);
        reinterpret_cast<float4*>(g_wsum)[blockIdx.x * 64 + t] = r;
    }
}

// ---------------- Kernel 3: batched rowdot ----------------
// One row per block, 256 threads. ALL 8 x LDG.128 issue back-to-back into
// registers (clean front-batched burst, no interleaved FMAs) BEFORE wsum is
// touched — the R16 schedule that hit 5.5 TB/s, without PDL.
__global__ __launch_bounds__(256) void rowdot(const float* __restrict__ x,
                                              float* __restrict__ out) {
    const int b = blockIdx.x;
    const float4* __restrict__ x4 =
        reinterpret_cast<const float4*>(x + (size_t)b * IN_DIM);

    // Phase 1: batch all x loads into registers
    float4 xv[COL4 / 256];
    #pragma unroll
    for (int k = 0; k < COL4 / 256; ++k)
        xv[k] = __ldg(&x4[threadIdx.x + k * 256]);

    // Phase 2: wsum loads + FMAs
    const float4* __restrict__ w4 = reinterpret_cast<const float4*>(g_wsum);
    float acc = 0.f;
    #pragma unroll
    for (int k = 0; k < COL4 / 256; ++k) {
        float4 wv = w4[threadIdx.x + k * 256];
        acc = fmaf(xv[k].x, wv.x, acc);
        acc = fmaf(xv[k].y, wv.y, acc);
        acc = fmaf(xv[k].z, wv.z, acc);
        acc = fmaf(xv[k].w, wv.w, acc);
    }

    #pragma unroll
    for (int off = 16; off > 0; off >>= 1)
        acc += __shfl_xor_sync(0xFFFFFFFFu, acc, off);

    __shared__ float warp_sums[8];
    const int lane = threadIdx.x & 31;
    const int wid  = threadIdx.x >> 5;
    if (lane == 0) warp_sums[wid] = acc;
    __syncthreads();

    if (wid == 0) {
        float v = (lane < 8) ? warp_sums[lane] : 0.f;
        #pragma unroll
        for (int off = 4; off > 0; off >>= 1)
            v += __shfl_xor_sync(0xFFFFFFFFu, v, off);
        if (lane == 0) out[b] = v * 0.75f;   // (/2) * 1.5
    }
}

extern "C" void kernel_launch(void* const* d_in, const int* in_sizes, int n_in,
                              void* d_out, int out_size) {
    const float* x = (const float*)d_in[0];   // [B, IN]
    const float* w = (const float*)d_in[1];   // [HID, IN]
    float* out = (float*)d_out;               // [B, 1]
    const int B = in_sizes[0] / IN_DIM;

    dim3 g1(COL4 / 256, ROW_GRPS);            // (8, 128)
    colsum_partial<<<g1, 256>>>(w);
    reduce_partial<<<32, 256>>>();
    rowdot<<<B, 256>>>(x, out);
}